// round 16
// baseline (speedup 1.0000x reference)
#include <cuda_runtime.h>
#include <math.h>

#define NNODE 6000
#define DIM   128
#define RREL  1000
#define NHEAD 2
#define LSEQ  3
#define KMAX  128
#define MAXNF 0.996f

// ---------------- scratch pool ----------------
#define O_ECOLS 0L                            // int [2][NNODE][KMAX]
#define O_EVALS (O_ECOLS + 1536000L)
#define O_ECNT  (O_EVALS + 1536000L)          // int [2][NNODE]
#define O_REL   (O_ECNT + 12032L)             // float[2][NNODE][DIM]
#define O_SEQ   (O_REL + 1536000L)            // float[2][NNODE][LSEQ][DIM]
#define O_HF    (O_SEQ + 4608000L)            // float[2][NHEAD][NNODE][DIM]
#define O_ES    (O_HF + 3072000L)             // float[2*NHEAD*NNODE]
#define O_ED    (O_ES + 24064L)
#define O_Y     (O_ED + 24064L)               // float[2][36000][128]
#define O_Z     (O_Y + 9216000L)              // float[36000][256]
#define O_OP    (O_Z + 9216000L)              // float[36000][128]
#define O_MV    (O_OP + 4608000L)             // float[2][NNODE][DIM]
#define O_T2    (O_MV + 1536000L)
#define O_TOUT  (O_T2 + 1536000L)
#define O_WT    (O_TOUT + 1536000L)           // float[2*DIM*DIM]
#define O_HB    (O_WT + 32768L)
#define O_HBN2  (O_HB + 256L)
#define O_A     (O_HBN2 + 32L)                // float[2][128][128]
#define O_G     (O_A + 32768L)                // float[256][128]
#define TOTALF  (O_G + 32768L)

__device__ __align__(256) float g_buf[TOTALF];

// ---------------- block reduction helpers (128 active threads) -------------
__device__ __forceinline__ float bsum(float v, float* sh) {
#pragma unroll
    for (int o = 16; o; o >>= 1) v += __shfl_xor_sync(0xffffffffu, v, o);
    int w = threadIdx.x >> 5;
    if ((threadIdx.x & 31) == 0) sh[w] = v;
    __syncthreads();
    float r = sh[0] + sh[1] + sh[2] + sh[3];
    __syncthreads();
    return r;
}

__device__ __forceinline__ void bsum2(float a, float b, float* sh, float* ra, float* rb) {
#pragma unroll
    for (int o = 16; o; o >>= 1) {
        a += __shfl_xor_sync(0xffffffffu, a, o);
        b += __shfl_xor_sync(0xffffffffu, b, o);
    }
    int w = threadIdx.x >> 5;
    if ((threadIdx.x & 31) == 0) { sh[w] = a; sh[4 + w] = b; }
    __syncthreads();
    *ra = sh[0] + sh[1] + sh[2] + sh[3];
    *rb = sh[4] + sh[5] + sh[6] + sh[7];
    __syncthreads();
}

// 256-thread variant: threads >=128 must pass v = 0
__device__ __forceinline__ float bsum256(float v, float* sh) {
#pragma unroll
    for (int o = 16; o; o >>= 1) v += __shfl_xor_sync(0xffffffffu, v, o);
    int w = threadIdx.x >> 5;
    if ((threadIdx.x & 31) == 0) sh[w] = v;
    __syncthreads();
    float r = sh[0] + sh[1] + sh[2] + sh[3];
    __syncthreads();
    return r;
}

// ---------------- mega setup kernel: all independent preprocessing ---------
#define NB_PREP 32
#define NB_SETW 258
#define NB_ELL  1500
#define NB_REL  12000
#define NB_INIT 12000
#define NB_TOTAL (NB_PREP + NB_SETW + NB_ELL + NB_REL + NB_INIT)

__global__ __launch_bounds__(256) void setup_all_k(
    const float* __restrict__ adj0, const float* __restrict__ adj1,
    const float* __restrict__ radj0, const float* __restrict__ radj1,
    const float* __restrict__ rel0, const float* __restrict__ rel1,
    const float* __restrict__ hgcW, const float* __restrict__ hgcb,
    const float* __restrict__ Wq, const float* __restrict__ Wk,
    const float* __restrict__ Wv, const float* __restrict__ Wfc,
    const float* __restrict__ e0, const float* __restrict__ e1,
    int* __restrict__ ecols, float* __restrict__ evals, int* __restrict__ ecnt,
    float* __restrict__ grel, float* __restrict__ WT, float* __restrict__ hb,
    float* __restrict__ hbn2, float* __restrict__ Am, float* __restrict__ G,
    float* __restrict__ seq, float* __restrict__ tout) {
    __shared__ __align__(16) char smraw[18688];
    int bid = blockIdx.x;
    int tid = threadIdx.x;

    if (bid < NB_PREP) {
        float (*sA)[33] = reinterpret_cast<float(*)[33]>(smraw);
        float (*sB)[129] = reinterpret_cast<float(*)[129]>(smraw + 2112);
        int mat = bid >> 3;
        int h = mat & 1;
        int row0 = (bid & 7) * 16;
        int r = tid >> 4;
        int cb = tid & 15;
        float acc[8] = {};
        const float* Asrc = (mat < 2) ? Wq : Wv;
        for (int k0 = 0; k0 < 128; k0 += 32) {
            for (int i = tid; i < 16 * 32; i += 256) {
                int rr = i >> 5, jj = i & 31;
                sA[rr][jj] = Asrc[(row0 + rr) * 256 + h * 128 + k0 + jj];
            }
            if (mat < 2) {
                for (int i = tid; i < 32 * 128; i += 256) {
                    int t = i >> 5, jj = i & 31;
                    sB[jj][t] = Wk[t * 256 + h * 128 + k0 + jj];
                }
            } else {
                for (int i = tid; i < 32 * 128; i += 256) {
                    int jj = i >> 7, t = i & 127;
                    sB[jj][t] = Wfc[(h * 128 + k0 + jj) * 128 + t];
                }
            }
            __syncthreads();
#pragma unroll
            for (int j = 0; j < 32; j++) {
                float a = sA[r][j];
#pragma unroll
                for (int i = 0; i < 8; i++) acc[i] += a * sB[j][cb + 16 * i];
            }
            __syncthreads();
        }
        float scale = (mat < 2) ? 0.08838834764831845f : 1.f;
        float* dst = ((mat < 2) ? Am : G) + (long)(h * 128 + row0 + r) * 128;
#pragma unroll
        for (int i = 0; i < 8; i++) dst[cb + 16 * i] = acc[i] * scale;
        return;
    }
    bid -= NB_PREP;

    if (bid < NB_SETW) {
        if (tid >= 128) return;
        float* sh = (float*)smraw;
        int i = bid & 1, yy = bid >> 1, d = tid;
        if (yy < 128) {
            WT[(long)i * 16384 + (long)d * 128 + yy] = hgcW[(long)i * 16384 + (long)yy * 128 + d];
        } else {
            float v = hgcb[i * DIM + d];
            float ss = bsum(v * v, sh);
            float nn = fmaxf(sqrtf(ss), 1e-15f);
            float t = tanhf(nn);
            float a = t / nn;
            if (t > MAXNF) a *= MAXNF / t;
            float hv = a * v;
            hb[i * DIM + d] = hv;
            float s2 = bsum(hv * hv, sh);
            if (!d) hbn2[i] = s2;
        }
        return;
    }
    bid -= NB_SETW;

    if (bid < NB_ELL) {
        int b = bid / 750;
        const float* adj = b ? adj1 : adj0;
        long off = (long)b * NNODE;
        int row = (bid % 750) * 8 + (tid >> 5);
        int lane = tid & 31;
        const float* arow = adj + (long)row * NNODE;
        int c = 0;
        for (int base = 0; base < NNODE; base += 128) {
            int col = base + lane * 4;
            float4 v = make_float4(0.f, 0.f, 0.f, 0.f);
            if (col < NNODE) v = *reinterpret_cast<const float4*>(arow + col);
            float vv[4] = {v.x, v.y, v.z, v.w};
            int lc = (vv[0] != 0.f) + (vv[1] != 0.f) + (vv[2] != 0.f) + (vv[3] != 0.f);
            int pre = lc;
#pragma unroll
            for (int o = 1; o < 32; o <<= 1) {
                int t = __shfl_up_sync(0xffffffffu, pre, o);
                if (lane >= o) pre += t;
            }
            int tot = __shfl_sync(0xffffffffu, pre, 31);
            int p = c + pre - lc;
#pragma unroll
            for (int i = 0; i < 4; i++)
                if (vv[i] != 0.f && p < KMAX) {
                    ecols[(off + row) * KMAX + p] = col + i;
                    evals[(off + row) * KMAX + p] = vv[i];
                    p++;
                }
            c += tot;
        }
        if (!lane) ecnt[off + row] = (c < KMAX) ? c : KMAX;
        return;
    }
    bid -= NB_ELL;

    if (bid < NB_REL) {
        if (tid >= 128) return;
        int* sidx = (int*)smraw;
        int* wsum = (int*)(smraw + 1024);
        int b = bid / NNODE;
        const float* radj = b ? radj1 : radj0;
        const float* rel = b ? rel1 : rel0;
        int row = bid % NNODE, t = tid, lane = t & 31, w = t >> 5;
        int base = t * 8;
        float e[8];
#pragma unroll
        for (int i = 0; i < 8; i++) e[i] = 0.f;
        if (base < RREL) {
            float4 v0 = *reinterpret_cast<const float4*>(radj + (long)row * RREL + base);
            float4 v1 = *reinterpret_cast<const float4*>(radj + (long)row * RREL + base + 4);
            e[0] = v0.x; e[1] = v0.y; e[2] = v0.z; e[3] = v0.w;
            e[4] = v1.x; e[5] = v1.y; e[6] = v1.z; e[7] = v1.w;
        }
        int lc = 0;
#pragma unroll
        for (int i = 0; i < 8; i++) lc += (e[i] != 0.f);
        int pre = lc;
#pragma unroll
        for (int o = 1; o < 32; o <<= 1) {
            int s = __shfl_up_sync(0xffffffffu, pre, o);
            if (lane >= o) pre += s;
        }
        if (lane == 31) wsum[w] = pre;
        __syncthreads();
        int boff = 0;
        for (int k = 0; k < w; k++) boff += wsum[k];
        int total = wsum[0] + wsum[1] + wsum[2] + wsum[3];
        int p = boff + pre - lc;
#pragma unroll
        for (int i = 0; i < 8; i++)
            if (e[i] != 0.f && p < 256) sidx[p++] = base + i;
        __syncthreads();
        float acc = 0.f;
        for (int j = 0; j < total; j++) acc += rel[(long)sidx[j] * DIM + t];
        grel[((long)b * NNODE + row) * DIM + t] = acc / (float)total;
        return;
    }
    bid -= NB_REL;

    if (tid >= 128) return;
    {
        float* sh = (float*)smraw;
        int b = bid / NNODE;
        int n = bid % NNODE, d = tid;
        const float* x = b ? e1 : e0;
        float v = x[(long)n * DIM + d];
        long r = (long)b * NNODE + n;
        seq[r * LSEQ * DIM + d] = v;
        float ss = bsum(v * v, sh);
        float nn = fmaxf(sqrtf(ss), 1e-15f);
        float t = tanhf(nn);
        float a = t / nn;
        if (t > MAXNF) a = MAXNF / nn;
        float np = fmaxf(a * nn, 1e-15f);
        float s = atanhf(fminf(np, 1.0f - 1e-7f)) / np;
        tout[r * DIM + d] = s * a * v;
    }
}

// ---------------- tf32 tensor-core GEMM, 128x128x16 tiles ------------------
__device__ __forceinline__ unsigned cvt_tf32(float f) {
    unsigned r;
    asm("cvt.rna.tf32.f32 %0, %1;" : "=r"(r) : "f"(f));
    return r;
}

__device__ __forceinline__ void mma_tf32(float c[4], const unsigned a[4], const unsigned b[2]) {
    asm volatile(
        "mma.sync.aligned.m16n8k8.row.col.f32.tf32.tf32.f32 "
        "{%0,%1,%2,%3}, {%4,%5,%6,%7}, {%8,%9}, {%0,%1,%2,%3};"
        : "+f"(c[0]), "+f"(c[1]), "+f"(c[2]), "+f"(c[3])
        : "r"(a[0]), "r"(a[1]), "r"(a[2]), "r"(a[3]), "r"(b[0]), "r"(b[1]));
}

__global__ __launch_bounds__(256) void gemm_tc_k(
    const float* __restrict__ A, const float* __restrict__ B, float* __restrict__ C,
    int M, int Ncols, int K, int lda, int ldb, int ldc,
    long sA, int divA, long sB, int modB, long sC) {
    int z = blockIdx.z;
    A += (long)(z / divA) * sA;
    B += (long)(z % modB) * sB;
    C += (long)z * sC;
    __shared__ unsigned As[16][136];
    __shared__ unsigned Bs[16][136];
    int tid = threadIdx.x;
    int warp = tid >> 5, lane = tid & 31;
    int gid = lane >> 2, tig = lane & 3;
    int wr = (warp & 3) * 32;
    int wc = (warp >> 2) * 64;
    int brow = blockIdx.y * 128, bcol = blockIdx.x * 128;

    int am = tid & 127;
    int akg = tid >> 7;
    int bn4 = (tid & 31) * 4;
    int bkr = tid >> 5;

    float4 aR0, aR1, bR0, bR1;

    {
        int gr = brow + am;
        if (gr < M) {
            const float* p = A + (long)gr * lda + akg * 8;
            aR0 = *reinterpret_cast<const float4*>(p);
            aR1 = *reinterpret_cast<const float4*>(p + 4);
        } else {
            aR0 = aR1 = make_float4(0.f, 0.f, 0.f, 0.f);
        }
        const float* q = B + (long)bkr * ldb + bcol + bn4;
        bR0 = *reinterpret_cast<const float4*>(q);
        bR1 = *reinterpret_cast<const float4*>(q + 8L * ldb);
    }

    float acc[2][8][4] = {};

    for (int k0 = 0; k0 < K; k0 += 16) {
        As[akg * 8 + 0][am] = cvt_tf32(aR0.x);
        As[akg * 8 + 1][am] = cvt_tf32(aR0.y);
        As[akg * 8 + 2][am] = cvt_tf32(aR0.z);
        As[akg * 8 + 3][am] = cvt_tf32(aR0.w);
        As[akg * 8 + 4][am] = cvt_tf32(aR1.x);
        As[akg * 8 + 5][am] = cvt_tf32(aR1.y);
        As[akg * 8 + 6][am] = cvt_tf32(aR1.z);
        As[akg * 8 + 7][am] = cvt_tf32(aR1.w);
        uint4 bb0 = make_uint4(cvt_tf32(bR0.x), cvt_tf32(bR0.y), cvt_tf32(bR0.z), cvt_tf32(bR0.w));
        uint4 bb1 = make_uint4(cvt_tf32(bR1.x), cvt_tf32(bR1.y), cvt_tf32(bR1.z), cvt_tf32(bR1.w));
        *reinterpret_cast<uint4*>(&Bs[bkr][bn4]) = bb0;
        *reinterpret_cast<uint4*>(&Bs[bkr + 8][bn4]) = bb1;
        __syncthreads();

        if (k0 + 16 < K) {
            int gr = brow + am;
            if (gr < M) {
                const float* p = A + (long)gr * lda + k0 + 16 + akg * 8;
                aR0 = *reinterpret_cast<const float4*>(p);
                aR1 = *reinterpret_cast<const float4*>(p + 4);
            }
            const float* q = B + (long)(k0 + 16 + bkr) * ldb + bcol + bn4;
            bR0 = *reinterpret_cast<const float4*>(q);
            bR1 = *reinterpret_cast<const float4*>(q + 8L * ldb);
        }

#pragma unroll
        for (int kk = 0; kk < 16; kk += 8) {
            unsigned af[2][4];
#pragma unroll
            for (int mi = 0; mi < 2; mi++) {
                int m = wr + mi * 16;
                af[mi][0] = As[kk + tig][m + gid];
                af[mi][1] = As[kk + tig][m + gid + 8];
                af[mi][2] = As[kk + tig + 4][m + gid];
                af[mi][3] = As[kk + tig + 4][m + gid + 8];
            }
            unsigned bf[8][2];
#pragma unroll
            for (int ni = 0; ni < 8; ni++) {
                int n = wc + ni * 8;
                bf[ni][0] = Bs[kk + tig][n + gid];
                bf[ni][1] = Bs[kk + tig + 4][n + gid];
            }
#pragma unroll
            for (int mi = 0; mi < 2; mi++)
#pragma unroll
                for (int ni = 0; ni < 8; ni++) mma_tf32(acc[mi][ni], af[mi], bf[ni]);
        }
        __syncthreads();
    }

#pragma unroll
    for (int mi = 0; mi < 2; mi++) {
        int r0 = brow + wr + mi * 16 + gid;
#pragma unroll
        for (int ni = 0; ni < 8; ni++) {
            int c0 = bcol + wc + ni * 8 + tig * 2;
            if (r0 < M)
                *reinterpret_cast<float2*>(C + (long)r0 * ldc + c0) =
                    make_float2(acc[mi][ni][0], acc[mi][ni][1]);
            if (r0 + 8 < M)
                *reinterpret_cast<float2*>(C + (long)(r0 + 8) * ldc + c0) =
                    make_float2(acc[mi][ni][2], acc[mi][ni][3]);
        }
    }
}

// ---------------- GAT: es/ed dot products (batched, float4) ----------------
__global__ void esd_k(const float* __restrict__ hf, const float* __restrict__ as,
                      const float* __restrict__ ad, float* __restrict__ es,
                      float* __restrict__ ed) {
    int n = blockIdx.x, b = blockIdx.y;
    int h = threadIdx.x >> 5, lane = threadIdx.x & 31;
    const float4* r = reinterpret_cast<const float4*>(hf + ((long)(b * NHEAD + h) * NNODE + n) * DIM);
    const float4* a4 = reinterpret_cast<const float4*>(as + h * DIM);
    const float4* d4 = reinterpret_cast<const float4*>(ad + h * DIM);
    float4 v = r[lane];
    float4 av = a4[lane];
    float4 dv = d4[lane];
    float s = v.x * av.x + v.y * av.y + v.z * av.z + v.w * av.w;
    float t = v.x * dv.x + v.y * dv.y + v.z * dv.z + v.w * dv.w;
#pragma unroll
    for (int o = 16; o; o >>= 1) {
        s += __shfl_xor_sync(0xffffffffu, s, o);
        t += __shfl_xor_sync(0xffffffffu, t, o);
    }
    if (!lane) {
        es[(long)(b * NHEAD + h) * NNODE + n] = s;
        ed[(long)(b * NHEAD + h) * NNODE + n] = t;
    }
}

// ---------------- GAT aggregate: 256 threads, head-split gather ------------
__global__ __launch_bounds__(256) void gat_agg_k(
    const int* __restrict__ cols, const int* __restrict__ cnt,
    const float* __restrict__ hf, const float* __restrict__ es,
    const float* __restrict__ ed, float* __restrict__ seq, int slot) {
    __shared__ int sc[KMAX];
    __shared__ float sw0[KMAX];
    __shared__ float sw1[KMAX];
    __shared__ float sacc[256];
    __shared__ float sh[8];
    int n = blockIdx.x, b = blockIdx.y, tid = threadIdx.x;
    long goff = (long)b * NNODE;
    int c = cnt[goff + n];
    for (int j = tid; j < c; j += 256) sc[j] = cols[(goff + n) * KMAX + j];
    __syncthreads();
    int w = tid >> 5, lane = tid & 31;
    if (w < NHEAD) {
        float* sw = w ? sw1 : sw0;
        const float* edp = ed + (long)(b * NHEAD + w) * NNODE;
        float e0 = es[(long)(b * NHEAD + w) * NNODE + n];
        float m = -1e30f;
        for (int j = lane; j < c; j += 32) {
            float e = e0 + edp[sc[j]];
            e = e > 0.f ? e : 0.2f * e;
            sw[j] = e;
            m = fmaxf(m, e);
        }
#pragma unroll
        for (int o = 16; o; o >>= 1) m = fmaxf(m, __shfl_xor_sync(0xffffffffu, m, o));
        float s = 0.f;
        for (int j = lane; j < c; j += 32) {
            float e = expf(sw[j] - m);
            sw[j] = e;
            s += e;
        }
#pragma unroll
        for (int o = 16; o; o >>= 1) s += __shfl_xor_sync(0xffffffffu, s, o);
        float inv = 1.f / s;
        for (int j = lane; j < c; j += 32) sw[j] *= inv;
    }
    __syncthreads();
    // gather: each thread handles ONE head (tid>>7) and one dim (tid&127)
    int h = tid >> 7, d = tid & 127;
    const float* hfh = hf + (long)(b * NHEAD + h) * NNODE * DIM + d;
    const float* sw = h ? sw1 : sw0;
    float p0 = 0.f, p1 = 0.f, p2 = 0.f, p3 = 0.f;
    int j = 0;
    for (; j + 4 <= c; j += 4) {
        long r0 = (long)sc[j] * DIM, r1 = (long)sc[j + 1] * DIM;
        long r2 = (long)sc[j + 2] * DIM, r3 = (long)sc[j + 3] * DIM;
        p0 += sw[j] * hfh[r0];
        p1 += sw[j + 1] * hfh[r1];
        p2 += sw[j + 2] * hfh[r2];
        p3 += sw[j + 3] * hfh[r3];
    }
    for (; j < c; j++) p0 += sw[j] * hfh[(long)sc[j] * DIM];
    sacc[tid] = (p0 + p1) + (p2 + p3);
    __syncthreads();
    float v = 0.f;
    if (tid < 128) {
        v = 0.5f * (sacc[tid] + sacc[tid + 128]);
        v = v > 0.f ? v : expm1f(v);
    }
    float ss = bsum256((tid < 128) ? v * v : 0.f, sh);
    if (tid < 128) {
        float nrm = fmaxf(sqrtf(ss), 1e-12f);
        seq[((goff + n) * LSEQ + slot) * DIM + tid] = v / nrm;
    }
}

// ---------------- attention: e = y.x dots, softmax, z = attn @ x -----------
__global__ void attn_z_k(const float* __restrict__ seq, const float* __restrict__ y,
                         float* __restrict__ z) {
    __shared__ float sx[LSEQ][DIM];
    __shared__ float sy[NHEAD][LSEQ][DIM];
    __shared__ float se[NHEAD][LSEQ][LSEQ];
    int r = blockIdx.x, tid = threadIdx.x, w = tid >> 5, lane = tid & 31;
    long r3 = (long)r * LSEQ;
    for (int i = tid; i < LSEQ * DIM; i += 128) sx[i >> 7][i & 127] = seq[r3 * DIM + i];
    for (int i = tid; i < NHEAD * LSEQ * DIM; i += 128) {
        int h = i / (LSEQ * DIM), rem = i % (LSEQ * DIM);
        sy[h][rem >> 7][rem & 127] = y[(long)h * 4608000L + r3 * DIM + rem];
    }
    __syncthreads();
    for (int idx = w; idx < NHEAD * LSEQ * LSEQ; idx += 4) {
        int h = idx / 9, rem = idx % 9, l = rem / 3, m = rem % 3;
        float s = 0.f;
#pragma unroll
        for (int d = lane; d < DIM; d += 32) s += sy[h][l][d] * sx[m][d];
#pragma unroll
        for (int o = 16; o; o >>= 1) s += __shfl_xor_sync(0xffffffffu, s, o);
        if (!lane) se[h][l][m] = s;
    }
    __syncthreads();
    if (tid < NHEAD * LSEQ) {
        int h = tid / 3, l = tid % 3;
        float m = fmaxf(se[h][l][0], fmaxf(se[h][l][1], se[h][l][2]));
        float e0 = expf(se[h][l][0] - m), e1 = expf(se[h][l][1] - m), e2 = expf(se[h][l][2] - m);
        float inv = 1.f / (e0 + e1 + e2);
        se[h][l][0] = e0 * inv;
        se[h][l][1] = e1 * inv;
        se[h][l][2] = e2 * inv;
    }
    __syncthreads();
    int d = tid;
    for (int l = 0; l < LSEQ; l++)
#pragma unroll
        for (int h = 0; h < NHEAD; h++) {
            float a = se[h][l][0] * sx[0][d] + se[h][l][1] * sx[1][d] + se[h][l][2] * sx[2][d];
            z[(r3 + l) * 256 + h * DIM + d] = a;
        }
}

// ---------------- MHA epilogue (batched) ----------------
__global__ void mha_epi_k(const float* __restrict__ op, const float* __restrict__ seq,
                          const float* __restrict__ relb, const float* __restrict__ lng,
                          const float* __restrict__ lnb, float* __restrict__ out) {
    __shared__ float sh[8];
    int n = blockIdx.x, b = blockIdx.y, d = threadIdx.x;
    long r = (long)b * NNODE + n;
    float acc = 0.f;
    for (int l = 0; l < LSEQ; l++) {
        long idx = (r * LSEQ + l) * DIM + d;
        float v = op[idx] + seq[idx];
        float mu = bsum(v, sh) * (1.f / DIM);
        float dv = v - mu;
        float var = bsum(dv * dv, sh) * (1.f / DIM);
        acc += lng[d] * dv * rsqrtf(var + 1e-6f) + lnb[d];
    }
    float* row = out + (long)b * NNODE * 2 * DIM + (long)n * 2 * DIM;
    row[d] = acc * (1.f / 3.f);
    row[DIM + d] = relb[r * DIM + d];
}

// expmap0+proj, mobius_add(.,hb), proj, logmap0 (batched)
__global__ void hgc_mid_k(const float* __restrict__ mv, const float* __restrict__ hb,
                          const float* __restrict__ hbn2, int layer, float* __restrict__ t2) {
    __shared__ float sh[8];
    int n = blockIdx.x, b = blockIdx.y, d = threadIdx.x;
    long r = (long)b * NNODE + n;
    float x0 = mv[r * DIM + d];
    float hbv = hb[layer * DIM + d];
    float y2 = hbn2[layer];
    float ss = bsum(x0 * x0, sh);
    float nn = fmaxf(sqrtf(ss), 1e-15f);
    float t = tanhf(nn);
    float a = t / nn;
    if (t > MAXNF) a *= MAXNF / t;
    float xd = a * x0;
    float x2, xy;
    bsum2(xd * xd, xd * hbv, sh, &x2, &xy);
    float num = (1.f + 2.f * xy + y2) * xd + (1.f - x2) * hbv;
    float den = fmaxf(1.f + 2.f * xy + x2 * y2, 1e-15f);
    float h2 = num / den;
    float ss2 = bsum(h2 * h2, sh);
    float nh = fmaxf(sqrtf(ss2), 1e-15f);
    float c = 1.f, npn = nh;
    if (nh > MAXNF) { c = MAXNF / nh; npn = MAXNF; }
    float p = fmaxf(npn, 1e-15f);
    float s = atanhf(fminf(p, 1.0f - 1e-7f)) / p;
    t2[r * DIM + d] = s * c * h2;
}

// sparse agg + hyperbolic chain fused; last writes final output rows
__global__ void hgc_agg_k(const int* __restrict__ cols, const float* __restrict__ vals,
                          const int* __restrict__ cnt, const float* __restrict__ tin,
                          float* __restrict__ tout, int last,
                          const float* __restrict__ e0, const float* __restrict__ e1,
                          const float* __restrict__ relb, float* __restrict__ out) {
    __shared__ int sc[KMAX];
    __shared__ float svv[KMAX];
    __shared__ float sh[8];
    int n = blockIdx.x, b = blockIdx.y, d = threadIdx.x;
    long goff = (long)b * NNODE;
    int c = cnt[goff + n];
    for (int j = d; j < c; j += DIM) {
        sc[j] = cols[(goff + n) * KMAX + j];
        svv[j] = vals[(goff + n) * KMAX + j];
    }
    __syncthreads();
    const float* tb = tin + goff * DIM + d;
    float q0 = 0.f, q1 = 0.f, q2 = 0.f, q3 = 0.f;
    float q4 = 0.f, q5 = 0.f, q6 = 0.f, q7 = 0.f;
    int j = 0;
    for (; j + 8 <= c; j += 8) {
        long r0 = (long)sc[j] * DIM, r1 = (long)sc[j + 1] * DIM;
        long r2 = (long)sc[j + 2] * DIM, r3 = (long)sc[j + 3] * DIM;
        long r4 = (long)sc[j + 4] * DIM, r5 = (long)sc[j + 5] * DIM;
        long r6 = (long)sc[j + 6] * DIM, r7 = (long)sc[j + 7] * DIM;
        q0 += svv[j] * tb[r0];
        q1 += svv[j + 1] * tb[r1];
        q2 += svv[j + 2] * tb[r2];
        q3 += svv[j + 3] * tb[r3];
        q4 += svv[j + 4] * tb[r4];
        q5 += svv[j + 5] * tb[r5];
        q6 += svv[j + 6] * tb[r6];
        q7 += svv[j + 7] * tb[r7];
    }
    for (; j < c; j++) q0 += svv[j] * tb[(long)sc[j] * DIM];
    float acc = ((q0 + q1) + (q2 + q3)) + ((q4 + q5) + (q6 + q7));
    float ss = bsum(acc * acc, sh);
    float nn = fmaxf(sqrtf(ss), 1e-15f);
    float t = tanhf(nn);
    float a = t / nn;
    if (t > MAXNF) a *= MAXNF / t;
    float pd = a * acc;
    float rp = fmaxf(pd, 0.f);
    float p2, r2;
    bsum2(pd * pd, rp * rp, sh, &p2, &r2);
    float npn = fmaxf(sqrtf(p2), 1e-15f);
    float beta = atanhf(fminf(npn, 1.0f - 1e-7f)) / npn;
    float t3 = beta * rp;
    float n3 = fmaxf(beta * sqrtf(r2), 1e-15f);
    float tt = tanhf(n3);
    float aa = tt / n3;
    if (tt > MAXNF) aa *= MAXNF / tt;
    float nh = fmaxf(aa * n3, 1e-15f);
    float s2 = atanhf(fminf(nh, 1.0f - 1e-7f)) / nh;
    float tv = s2 * aa * t3;
    if (!last) {
        tout[(goff + n) * DIM + d] = tv;
    } else {
        const float* x = b ? e1 : e0;
        float* row = out + (long)b * NNODE * 2 * DIM + (long)n * 2 * DIM;
        row[d] = x[(long)n * DIM + d] + tv;
        row[DIM + d] = relb[(goff + n) * DIM + d];
    }
}

// ---------------- host ----------------
extern "C" void kernel_launch(void* const* d_in, const int* in_sizes, int n_in,
                              void* d_out, int out_size) {
    (void)in_sizes; (void)n_in; (void)out_size;
    const float* ent0 = (const float*)d_in[0];
    const float* ent1 = (const float*)d_in[1];
    const float* rel0 = (const float*)d_in[2];
    const float* rel1 = (const float*)d_in[3];
    const float* adj0 = (const float*)d_in[4];
    const float* adj1 = (const float*)d_in[5];
    const float* radj0 = (const float*)d_in[6];
    const float* radj1 = (const float*)d_in[7];
    const float* gatW = (const float*)d_in[8];
    const float* aS = (const float*)d_in[9];
    const float* aD = (const float*)d_in[10];
    const float* Wq = (const float*)d_in[11];
    const float* Wk = (const float*)d_in[12];
    const float* Wv = (const float*)d_in[13];
    const float* Wfc = (const float*)d_in[14];
    const float* lng = (const float*)d_in[15];
    const float* lnb = (const float*)d_in[16];
    const float* hgcW = (const float*)d_in[17];
    const float* hgcb = (const float*)d_in[18];
    float* out = (float*)d_out;

    float* base = nullptr;
    cudaGetSymbolAddress((void**)&base, g_buf);

    int* ecols = (int*)(base + O_ECOLS);
    float* evals = base + O_EVALS;
    int* ecnt = (int*)(base + O_ECNT);
    float* grel = base + O_REL;
    float* gseq = base + O_SEQ;
    float* ghf = base + O_HF;
    float* ges = base + O_ES;
    float* ged = base + O_ED;
    float* gy = base + O_Y;
    float* gz = base + O_Z;
    float* gop = base + O_OP;
    float* gmv = base + O_MV;
    float* gt2 = base + O_T2;
    float* gtout = base + O_TOUT;
    float* gwt = base + O_WT;
    float* ghb = base + O_HB;
    float* ghbn2 = base + O_HBN2;
    float* gA = base + O_A;
    float* gG = base + O_G;

    const long BSEQ = (long)NNODE * LSEQ * DIM;
    const long BND = (long)NNODE * DIM;

    // ---- one mega preprocessing launch ----
    setup_all_k<<<NB_TOTAL, 256>>>(adj0, adj1, radj0, radj1, rel0, rel1, hgcW, hgcb,
                                   Wq, Wk, Wv, Wfc, ent0, ent1,
                                   ecols, evals, ecnt, grel, gwt, ghb, ghbn2,
                                   gA, gG, gseq, gtout);

    // ---- GAT x2 layers ----
    for (int layer = 0; layer < 2; layer++) {
        gemm_tc_k<<<dim3(1, 47, 4), 256>>>(
            gseq + (long)layer * DIM, gatW + (long)layer * NHEAD * DIM * DIM, ghf,
            NNODE, DIM, DIM, LSEQ * DIM, DIM, DIM,
            BSEQ, NHEAD, (long)DIM * DIM, NHEAD, BND);
        esd_k<<<dim3(NNODE, 2), 64>>>(ghf, aS + layer * NHEAD * DIM, aD + layer * NHEAD * DIM,
                                      ges, ged);
        gat_agg_k<<<dim3(NNODE, 2), 256>>>(ecols, ecnt, ghf, ges, ged, gseq, layer + 1);
    }

    // ---- MHA via folded weights ----
    gemm_tc_k<<<dim3(1, 282, 2), 256>>>(gseq, gA, gy, 2 * NNODE * LSEQ, DIM, DIM,
                                        DIM, DIM, DIM, 0, 1, (long)DIM * DIM, 2,
                                        (long)2 * NNODE * LSEQ * DIM);
    attn_z_k<<<2 * NNODE, 128>>>(gseq, gy, gz);
    gemm_tc_k<<<dim3(1, 282, 1), 256>>>(gz, gG, gop, 2 * NNODE * LSEQ, DIM, 2 * DIM,
                                        2 * DIM, DIM, DIM, 0, 1, 0, 1, 0);
    mha_epi_k<<<dim3(NNODE, 2), DIM>>>(gop, gseq, grel, lng, lnb, out);

    // ---- hyperbolic encoder ----
    for (int i = 0; i < 2; i++) {
        gemm_tc_k<<<dim3(1, 47, 2), 256>>>(gtout, gwt + (long)i * DIM * DIM, gmv,
                                           NNODE, DIM, DIM, DIM, DIM, DIM,
                                           BND, 1, 0, 1, BND);
        hgc_mid_k<<<dim3(NNODE, 2), DIM>>>(gmv, ghb, ghbn2, i, gt2);
        hgc_agg_k<<<dim3(NNODE, 2), DIM>>>(ecols, evals, ecnt, gt2, gtout, i == 1,
                                           ent0, ent1, grel, out + 2L * NNODE * 2 * DIM);
    }
}